// round 1
// baseline (speedup 1.0000x reference)
#include <cuda_runtime.h>
#include <math.h>

// ---------------- problem constants ----------------
#define BB      8
#define TT      4096
#define DD      512
#define QQ      4
#define KK_CB   1024
#define KER     5
#define STRIDEC 2
#define TOUT    (TT / STRIDEC)           // 2048
#define NTOK    (BB * TT)                // 32768
#define NELEM   (NTOK * DD)              // 16777216
#define Y_SZ    (BB * TOUT * DD)         // 8388608
#define QO_SZ   NELEM                    // 16777216
#define IDX_SZ  (QQ * NTOK)              // 131072
#define LOSS_OFF (Y_SZ + QO_SZ + IDX_SZ)

// ---------------- persistent scratch ----------------
__device__ float  g_residual[NELEM];     // 64 MB
__device__ float  g_cnorm[QQ * KK_CB];
__device__ int    g_idx[QQ * NTOK];
__device__ double g_loss;

// ---------------- codebook norms (+loss reset) ----------------
__global__ void cnorm_kernel(const float* __restrict__ cb) {
    if (blockIdx.x == 0 && threadIdx.x == 0) g_loss = 0.0;
    int w    = (blockIdx.x * blockDim.x + threadIdx.x) >> 5;
    int lane = threadIdx.x & 31;
    if (w >= QQ * KK_CB) return;
    const float* c = cb + (size_t)w * DD;
    float s = 0.f;
    #pragma unroll
    for (int d = lane; d < DD; d += 32) { float v = c[d]; s += v * v; }
    #pragma unroll
    for (int o = 16; o > 0; o >>= 1) s += __shfl_down_sync(0xffffffffu, s, o);
    if (lane == 0) g_cnorm[w] = s;
}

// ---------------- VQ distance GEMM + argmin ----------------
// dist(token,k) = ||c_k||^2 - 2 * r . c_k   (token norm dropped: constant per row)
// Tile: 128 tokens x 128 codes, K-step 16, 8x8 microtile, 256 threads.
__global__ __launch_bounds__(256)
void vq_argmin_kernel(const float* __restrict__ x,
                      const float* __restrict__ cb_stage,   // [1024,512]
                      int stage) {
    __shared__ float As[16][132];
    __shared__ float Bs[16][132];
    __shared__ float red_d[128][17];
    __shared__ int   red_k[128][17];

    const float* A = (stage == 0) ? x : g_residual;
    const float* cn = g_cnorm + stage * KK_CB;

    int t  = threadIdx.x;
    int tx = t & 15, ty = t >> 4;
    int row0 = blockIdx.x * 128;

    float bestd[8];
    int   bestk[8];
    #pragma unroll
    for (int i = 0; i < 8; i++) { bestd[i] = 3.4e38f; bestk[i] = 0; }

    for (int nt = 0; nt < KK_CB / 128; ++nt) {
        float acc[8][8];
        #pragma unroll
        for (int i = 0; i < 8; i++)
            #pragma unroll
            for (int j = 0; j < 8; j++) acc[i][j] = 0.f;

        const float* Bbase = cb_stage + (size_t)nt * 128 * DD;

        for (int k0 = 0; k0 < DD; k0 += 16) {
            #pragma unroll
            for (int i = 0; i < 2; i++) {
                int idx = t + 256 * i;
                int r = idx >> 2, c = idx & 3;
                float4 va = *(const float4*)(A + (size_t)(row0 + r) * DD + k0 + 4 * c);
                As[4*c+0][r] = va.x; As[4*c+1][r] = va.y;
                As[4*c+2][r] = va.z; As[4*c+3][r] = va.w;
                float4 vb = *(const float4*)(Bbase + (size_t)r * DD + k0 + 4 * c);
                Bs[4*c+0][r] = vb.x; Bs[4*c+1][r] = vb.y;
                Bs[4*c+2][r] = vb.z; Bs[4*c+3][r] = vb.w;
            }
            __syncthreads();
            #pragma unroll
            for (int kk = 0; kk < 16; ++kk) {
                float a[8], b[8];
                *(float4*)(a)     = *(const float4*)&As[kk][ty * 8];
                *(float4*)(a + 4) = *(const float4*)&As[kk][ty * 8 + 4];
                *(float4*)(b)     = *(const float4*)&Bs[kk][tx * 8];
                *(float4*)(b + 4) = *(const float4*)&Bs[kk][tx * 8 + 4];
                #pragma unroll
                for (int i = 0; i < 8; i++)
                    #pragma unroll
                    for (int j = 0; j < 8; j++) acc[i][j] += a[i] * b[j];
            }
            __syncthreads();
        }
        // fold this code tile into per-thread argmin (ascending col order => ties keep first)
        #pragma unroll
        for (int i = 0; i < 8; i++) {
            #pragma unroll
            for (int j = 0; j < 8; j++) {
                int col = nt * 128 + tx * 8 + j;
                float d = __ldg(cn + col) - 2.0f * acc[i][j];
                if (d < bestd[i]) { bestd[i] = d; bestk[i] = col; }
            }
        }
    }
    #pragma unroll
    for (int i = 0; i < 8; i++) { red_d[ty*8+i][tx] = bestd[i]; red_k[ty*8+i][tx] = bestk[i]; }
    __syncthreads();
    if (t < 128) {
        float bd = red_d[t][0]; int bk = red_k[t][0];
        #pragma unroll
        for (int j = 1; j < 16; j++) {
            float d = red_d[t][j]; int k = red_k[t][j];
            if (d < bd || (d == bd && k < bk)) { bd = d; bk = k; }
        }
        g_idx[stage * NTOK + row0 + t] = bk;
    }
}

// ---------------- per-stage update: residual -= q, loss accumulation ----------------
__global__ void vq_update_kernel(const float* __restrict__ x,
                                 const float* __restrict__ cb_stage,
                                 int stage) {
    __shared__ float sred[256];
    const float4* src = (const float4*)((stage == 0) ? x : g_residual);
    float4* res = (float4*)g_residual;
    const float4* cb4 = (const float4*)cb_stage;
    const int* idx = g_idx + stage * NTOK;

    float lsum = 0.f;
    int n4 = NELEM / 4;
    for (int e = blockIdx.x * blockDim.x + threadIdx.x; e < n4; e += gridDim.x * blockDim.x) {
        int tok = e >> 7;          // 128 float4 per token
        int d4  = e & 127;
        int k   = __ldg(idx + tok);
        float4 r = src[e];
        float4 q = cb4[(size_t)k * 128 + d4];
        float dx = q.x - r.x, dy = q.y - r.y, dz = q.z - r.z, dw = q.w - r.w;
        lsum += dx * dx + dy * dy + dz * dz + dw * dw;
        res[e] = make_float4(-dx, -dy, -dz, -dw);   // r - q
    }
    sred[threadIdx.x] = lsum;
    __syncthreads();
    for (int o = 128; o > 0; o >>= 1) {
        if (threadIdx.x < o) sred[threadIdx.x] += sred[threadIdx.x + o];
        __syncthreads();
    }
    if (threadIdx.x == 0) atomicAdd(&g_loss, (double)sred[0]);
}

// ---------------- quantized_out = x - residual_final ----------------
__global__ void finish_quant_kernel(const float* __restrict__ x, float* __restrict__ quant) {
    int n4 = NELEM / 4;
    const float4* x4 = (const float4*)x;
    const float4* r4 = (const float4*)g_residual;
    float4* q4 = (float4*)quant;
    for (int e = blockIdx.x * blockDim.x + threadIdx.x; e < n4; e += gridDim.x * blockDim.x) {
        float4 a = x4[e], b = r4[e];
        q4[e] = make_float4(a.x - b.x, a.y - b.y, a.z - b.z, a.w - b.w);
    }
}

// ---------------- conv1d (stride 2, SAME, pad_lo=1) + exact GELU ----------------
// GEMM: out[16384,512] = patches[16384, 5*512] x W[5*512, 512]
__global__ __launch_bounds__(256)
void conv_gelu_kernel(const float* __restrict__ quant,
                      const float* __restrict__ W,
                      float* __restrict__ y) {
    __shared__ float As[16][132];
    __shared__ float Bs[16][132];

    int t  = threadIdx.x;
    int tx = t & 15, ty = t >> 4;
    int mrow0 = blockIdx.x * 128;
    int ncol0 = blockIdx.y * 128;

    float acc[8][8];
    #pragma unroll
    for (int i = 0; i < 8; i++)
        #pragma unroll
        for (int j = 0; j < 8; j++) acc[i][j] = 0.f;

    for (int kk = 0; kk < KER; ++kk) {
        const float* Wk = W + (size_t)kk * DD * DD;
        for (int c0 = 0; c0 < DD; c0 += 16) {
            #pragma unroll
            for (int i = 0; i < 2; i++) {
                int idx = t + 256 * i;
                // A tile: 128 out-rows x 16 channels
                int r = idx >> 2, c = idx & 3;
                int row = mrow0 + r;
                int b   = row >> 11;          // / TOUT
                int to  = row & (TOUT - 1);
                int tin = 2 * to + kk - 1;    // SAME: pad_lo = 1
                float4 va = make_float4(0.f, 0.f, 0.f, 0.f);
                if ((unsigned)tin < (unsigned)TT)
                    va = *(const float4*)(quant + ((size_t)b * TT + tin) * DD + c0 + 4 * c);
                As[4*c+0][r] = va.x; As[4*c+1][r] = va.y;
                As[4*c+2][r] = va.z; As[4*c+3][r] = va.w;
                // B tile: 16 in-channels x 128 out-channels (already [k][col] layout)
                int ci = idx >> 5, cq = idx & 31;
                float4 vb = *(const float4*)(Wk + (size_t)(c0 + ci) * DD + ncol0 + cq * 4);
                *(float4*)&Bs[ci][cq * 4] = vb;
            }
            __syncthreads();
            #pragma unroll
            for (int kki = 0; kki < 16; ++kki) {
                float a[8], b[8];
                *(float4*)(a)     = *(const float4*)&As[kki][ty * 8];
                *(float4*)(a + 4) = *(const float4*)&As[kki][ty * 8 + 4];
                *(float4*)(b)     = *(const float4*)&Bs[kki][tx * 8];
                *(float4*)(b + 4) = *(const float4*)&Bs[kki][tx * 8 + 4];
                #pragma unroll
                for (int i = 0; i < 8; i++)
                    #pragma unroll
                    for (int j = 0; j < 8; j++) acc[i][j] += a[i] * b[j];
            }
            __syncthreads();
        }
    }
    #pragma unroll
    for (int i = 0; i < 8; i++) {
        int row = mrow0 + ty * 8 + i;
        #pragma unroll
        for (int j = 0; j < 8; j++) {
            int co = ncol0 + tx * 8 + j;
            float v = acc[i][j];
            float g = 0.5f * v * (1.0f + erff(v * 0.70710678118654752f));
            y[(size_t)row * DD + co] = g;
        }
    }
}

// ---------------- indices (as float) + loss ----------------
__global__ void finalize_kernel(float* __restrict__ out) {
    int i = blockIdx.x * blockDim.x + threadIdx.x;
    if (i < IDX_SZ) out[Y_SZ + QO_SZ + i] = (float)g_idx[i];
    if (i == 0)     out[LOSS_OFF] = (float)(0.25 * g_loss / (double)NELEM);
}

// ---------------- launch ----------------
extern "C" void kernel_launch(void* const* d_in, const int* in_sizes, int n_in,
                              void* d_out, int out_size) {
    const float* x  = (const float*)d_in[0];
    const float* cb = (const float*)d_in[1];
    const float* w  = (const float*)d_in[2];
    float* out   = (float*)d_out;
    float* y     = out;
    float* quant = out + Y_SZ;

    cnorm_kernel<<<(QQ * KK_CB * 32 + 255) / 256, 256>>>(cb);
    for (int s = 0; s < QQ; ++s) {
        vq_argmin_kernel<<<NTOK / 128, 256>>>(x, cb + (size_t)s * KK_CB * DD, s);
        vq_update_kernel<<<2048, 256>>>(x, cb + (size_t)s * KK_CB * DD, s);
    }
    finish_quant_kernel<<<4096, 256>>>(x, quant);
    conv_gelu_kernel<<<dim3(BB * TOUT / 128, DD / 128), 256>>>(quant, w, y);
    finalize_kernel<<<(IDX_SZ + 255) / 256, 256>>>(out);
}